// round 5
// baseline (speedup 1.0000x reference)
#include <cuda_runtime.h>

#define FULLMASK 0xffffffffu

// ---- shared layout (float offsets), one 512-thread block, 64 points ----
#define W2_STRIDE 260
#define W1T_STRIDE 20
#define W1R_STRIDE 68
#define TH_STRIDE 68
#define HW_STRIDE 68          // hsc (stage1-2) / wsc (stage4-5) union
#define SV_STRIDE 28          // vsc, svsc
#define UD_STRIDE 24          // usc, dsc
#define TS 20
#define TILE 328              // 328 % 32 == 8

#define W2S_OFF 0                                   // 64*260 = 16640
#define W1T_OFF 16640                               // 64*20 = 1280
#define W1R_OFF 17920                               // 16*68 = 1088
#define B1S_OFF 19008                               // 64
#define B2S_OFF 19072                               // 256
#define TH_OFF  19328                               // 64*68 = 4352
#define HW_OFF  23680                               // 4352
#define VSC_OFF 28032                               // 64*28 = 1792
#define SVSC_OFF 29824                              // 1792
#define USC_OFF 31616                               // 64*24 = 1536
#define DSC_OFF 33152                               // 1536
#define TILES_OFF 34688                             // 64*328 = 20992
#define SMEM_FLOATS 55680
#define SMEM_BYTES (SMEM_FLOATS * 4)                // 222720

// One acceleration evaluation for the whole block (64 points), cooperative.
// Per-point ownership (stages 1, s, u, solve): warp owns 4 pts, lane=(g,sub).
// Returns (dv_sub, dv_{sub+8}) of point lp = warp*4+g.
__device__ __noinline__ float2 geo_dv(float xe0, float xe1, float ve0, float ve1,
                                      int lane, int sub, int g, int warp, int lp)
{
    extern __shared__ float smem[];
    const float* W2s = smem + W2S_OFF;
    const float* W1t = smem + W1T_OFF;
    const float* W1r = smem + W1R_OFF;
    const float* b1s = smem + B1S_OFF;
    const float* b2s = smem + B2S_OFF;
    float* thsc = smem + TH_OFF;
    float* hw   = smem + HW_OFF;     // h in stages 1-2, w in stages 4-5
    float* vsc  = smem + VSC_OFF;
    float* svsc = smem + SVSC_OFF;
    float* usc  = smem + USC_OFF;
    float* dsc  = smem + DSC_OFF;
    float* tiles = smem + TILES_OFF;

    const int gbase = lane & 24;

    // ================= stage 1: hidden layer (per-warp, 4 pts) =============
    __syncthreads();   // prev eval's tiles/hw/dsc consumers done

    float x[16], v[16];
#pragma unroll
    for (int a = 0; a < 8; a++) {
        x[a]     = __shfl_sync(FULLMASK, xe0, gbase + a);
        x[a + 8] = __shfl_sync(FULLMASK, xe1, gbase + a);
        v[a]     = __shfl_sync(FULLMASK, ve0, gbase + a);
        v[a + 8] = __shfl_sync(FULLMASK, ve1, gbase + a);
    }
#pragma unroll
    for (int j = 0; j < 8; j++) {
        const int c = sub + 8 * j;
        float pre = b1s[c];
        const float4* wr = (const float4*)(W1t + c * W1T_STRIDE);
#pragma unroll
        for (int t = 0; t < 4; t++) {
            const float4 w = wr[t];
            pre = fmaf(w.x, x[4 * t + 0], pre);
            pre = fmaf(w.y, x[4 * t + 1], pre);
            pre = fmaf(w.z, x[4 * t + 2], pre);
            pre = fmaf(w.w, x[4 * t + 3], pre);
        }
        const float hh = tanhf(pre);
        hw[lp * HW_STRIDE + c] = hh;
        thsc[lp * TH_STRIDE + c] = fmaf(-hh, hh, 1.0f);
    }
    vsc[lp * SV_STRIDE + sub] = ve0;
    vsc[lp * SV_STRIDE + sub + 8] = ve1;
    __syncthreads();   // h, th, v visible block-wide

    // ================= stage 2: A-GEMM (block): A = h @ W2 + b2 ============
    // warp: ptb=warp>>2 (16 pts), cb=warp&3 (64 flat cols).
    // lane: ptg=lane>>2 -> pts {ptb*16+ptg, +8}; cg=lane&3.
    // lane's cols: pq = cb*64 + 16m + 4cg + {0..3},  m=0..3  => p=cb*4+m, q=4cg.
    {
        const int ptb = warp >> 2;
        const int cb = warp & 3;
        const int ptg = lane >> 2;
        const int cg = lane & 3;
        const int p0 = ptb * 16 + ptg;
        const int p1 = p0 + 8;
        float4 acc0[4], acc1[4];
#pragma unroll
        for (int m = 0; m < 4; m++) {
            const float4 bz = *(const float4*)(b2s + cb * 64 + 16 * m + 4 * cg);
            acc0[m] = bz;
            acc1[m] = bz;
        }
        const float* hr0 = hw + p0 * HW_STRIDE;
        const float* hr1 = hw + p1 * HW_STRIDE;
        const float* w2c = W2s + cb * 64 + 4 * cg;
        for (int kc = 0; kc < 16; kc++) {
            const float4 h0 = *(const float4*)(hr0 + 4 * kc);
            const float4 h1 = *(const float4*)(hr1 + 4 * kc);
            const float* wk = w2c + (4 * kc) * W2_STRIDE;
#pragma unroll
            for (int kk = 0; kk < 4; kk++) {
                const float a0 = (kk == 0) ? h0.x : (kk == 1) ? h0.y : (kk == 2) ? h0.z : h0.w;
                const float a1 = (kk == 0) ? h1.x : (kk == 1) ? h1.y : (kk == 2) ? h1.z : h1.w;
                const float* wr = wk + kk * W2_STRIDE;
#pragma unroll
                for (int m = 0; m < 4; m++) {
                    const float4 w = *(const float4*)(wr + 16 * m);
                    acc0[m].x = fmaf(a0, w.x, acc0[m].x);
                    acc0[m].y = fmaf(a0, w.y, acc0[m].y);
                    acc0[m].z = fmaf(a0, w.z, acc0[m].z);
                    acc0[m].w = fmaf(a0, w.w, acc0[m].w);
                    acc1[m].x = fmaf(a1, w.x, acc1[m].x);
                    acc1[m].y = fmaf(a1, w.y, acc1[m].y);
                    acc1[m].z = fmaf(a1, w.z, acc1[m].z);
                    acc1[m].w = fmaf(a1, w.w, acc1[m].w);
                }
            }
        }
#pragma unroll
        for (int m = 0; m < 4; m++) {
            *(float4*)(tiles + p0 * TILE + (cb * 4 + m) * TS + 4 * cg) = acc0[m];
            *(float4*)(tiles + p1 * TILE + (cb * 4 + m) * TS + 4 * cg) = acc1[m];
        }
    }
    __syncthreads();   // tiles (A) ready

    // ================= stage 3: s = A^T v (per-warp, own point) ============
    {
        const float* myt = tiles + lp * TILE;
        float s0 = 0.0f, s1 = 0.0f;
#pragma unroll
        for (int p = 0; p < 16; p++) {
            s0 = fmaf(myt[p * TS + sub], v[p], s0);
            s1 = fmaf(myt[p * TS + sub + 8], v[p], s1);
        }
        svsc[lp * SV_STRIDE + sub] = s0;
        svsc[lp * SV_STRIDE + sub + 8] = s1;
    }
    __syncthreads();   // s ready block-wide

    // ================= stage 4: m-GEMM (block) =============================
    // Y[pt, c] = sum_pq v_p s_q W2[c, pq];  w = 2*th*Y  -> hw (wsc)
    // warp: ptb=warp>>1 (8 pts), cb=warp&1 (32 c).
    // lane: pt = ptb*8 + (lane>>2); cg=lane&3 -> c = cb*32 + cg + 4j, j<8.
    {
        const int ptM = (warp >> 1) * 8 + (lane >> 2);
        const int cg = lane & 3;
        const int cbase = (warp & 1) * 32 + cg;
        float sM[16], vM[16];
#pragma unroll
        for (int t = 0; t < 4; t++) {
            const float4 a = *(const float4*)(svsc + ptM * SV_STRIDE + 4 * t);
            const float4 b = *(const float4*)(vsc + ptM * SV_STRIDE + 4 * t);
            sM[4 * t + 0] = a.x; sM[4 * t + 1] = a.y; sM[4 * t + 2] = a.z; sM[4 * t + 3] = a.w;
            vM[4 * t + 0] = b.x; vM[4 * t + 1] = b.y; vM[4 * t + 2] = b.z; vM[4 * t + 3] = b.w;
        }
        float y[8];
#pragma unroll
        for (int j = 0; j < 8; j++) y[j] = 0.0f;
        const float* w2base = W2s + cbase * W2_STRIDE;
        for (int p = 0; p < 16; p++) {
            const float vp = vM[p];
            const float* wp = w2base + 16 * p;
#pragma unroll
            for (int u = 0; u < 4; u++) {
                const float c0 = vp * sM[4 * u + 0];
                const float c1 = vp * sM[4 * u + 1];
                const float c2 = vp * sM[4 * u + 2];
                const float c3 = vp * sM[4 * u + 3];
                const float* wu = wp + 4 * u;
#pragma unroll
                for (int j = 0; j < 8; j++) {
                    const float4 w = *(const float4*)(wu + j * 4 * W2_STRIDE);
                    y[j] = fmaf(c0, w.x, y[j]);
                    y[j] = fmaf(c1, w.y, y[j]);
                    y[j] = fmaf(c2, w.z, y[j]);
                    y[j] = fmaf(c3, w.w, y[j]);
                }
            }
        }
#pragma unroll
        for (int j = 0; j < 8; j++) {
            const int c = cbase + 4 * j;
            const float th = thsc[ptM * TH_STRIDE + c];
            hw[ptM * HW_STRIDE + c] = 2.0f * th * y[j];
        }
    }
    __syncthreads();   // w ready block-wide

    // ================= stage 5: u, then SPD solve (per-warp) ===============
    {
        float u0 = 0.0f, u1 = 0.0f;
        const float4* wr0 = (const float4*)(W1r + sub * W1R_STRIDE);
        const float4* wr1 = (const float4*)(W1r + (sub + 8) * W1R_STRIDE);
        const float4* wc = (const float4*)(hw + lp * HW_STRIDE);
#pragma unroll
        for (int t = 0; t < 16; t++) {
            const float4 cc = wc[t];
            const float4 a0 = wr0[t];
            const float4 a1 = wr1[t];
            u0 = fmaf(a0.x, cc.x, u0); u0 = fmaf(a0.y, cc.y, u0);
            u0 = fmaf(a0.z, cc.z, u0); u0 = fmaf(a0.w, cc.w, u0);
            u1 = fmaf(a1.x, cc.x, u1); u1 = fmaf(a1.y, cc.y, u1);
            u1 = fmaf(a1.z, cc.z, u1); u1 = fmaf(a1.w, cc.w, u1);
        }
        usc[lp * UD_STRIDE + sub] = u0;
        usc[lp * UD_STRIDE + sub + 8] = u1;
    }
    __syncwarp();

    const int half = lane >> 4;
    const int i16 = lane & 15;
#pragma unroll
    for (int r = 0; r < 2; r++) {
        const int lpg = warp * 4 + 2 * r + half;
        const float* T = tiles + lpg * TILE;

        float ar[16];
#pragma unroll
        for (int t = 0; t < 4; t++) {
            const float4 w = *(const float4*)(T + i16 * TS + 4 * t);
            ar[4 * t + 0] = w.x; ar[4 * t + 1] = w.y;
            ar[4 * t + 2] = w.z; ar[4 * t + 3] = w.w;
        }
        float grow[16];
#pragma unroll
        for (int jr = 0; jr < 16; jr++) {
            float gj = (jr == i16) ? 1.0f : 0.0f;
#pragma unroll
            for (int t = 0; t < 4; t++) {
                const float4 w = *(const float4*)(T + jr * TS + 4 * t);
                gj = fmaf(ar[4 * t + 0], w.x, gj);
                gj = fmaf(ar[4 * t + 1], w.y, gj);
                gj = fmaf(ar[4 * t + 2], w.z, gj);
                gj = fmaf(ar[4 * t + 3], w.w, gj);
            }
            grow[jr] = gj;
        }
        float rhs = usc[lpg * UD_STRIDE + i16];

#pragma unroll
        for (int k = 0; k < 15; k++) {
            const float piv = __shfl_sync(FULLMASK, grow[k], k, 16);
            const float prhs = __shfl_sync(FULLMASK, rhs, k, 16);
            const float ipiv = __fdividef(1.0f, piv);
            const float fac = grow[k] * ipiv;
            const bool act = (i16 > k);
#pragma unroll
            for (int q = k + 1; q < 16; q++) {
                const float pq = __shfl_sync(FULLMASK, grow[q], k, 16);
                if (act) grow[q] = fmaf(-fac, pq, grow[q]);
            }
            if (act) rhs = fmaf(-fac, prhs, rhs);
        }
        float dvl = 0.0f;
#pragma unroll
        for (int k = 15; k >= 0; k--) {
            const float num = __shfl_sync(FULLMASK, rhs, k, 16);
            const float den = __shfl_sync(FULLMASK, grow[k], k, 16);
            const float yk = __fdividef(num, den);
            if (i16 < k) rhs = fmaf(-grow[k], yk, rhs);
            if (i16 == k) dvl = -0.5f * yk;
        }
        dsc[lpg * UD_STRIDE + i16] = dvl;
    }
    __syncwarp();

    float2 res;
    res.x = dsc[lp * UD_STRIDE + sub];
    res.y = dsc[lp * UD_STRIDE + sub + 8];
    return res;
}

__global__ __launch_bounds__(512, 1)
void NeuralGeodesicFlows_45784351375900_kernel(
    const float* __restrict__ z_in,
    const float* __restrict__ t_ptr,
    const float* __restrict__ W1,
    const float* __restrict__ b1,
    const float* __restrict__ W2,
    const float* __restrict__ b2,
    const int* __restrict__ ns_ptr,
    float* __restrict__ z_out,
    int B)
{
    extern __shared__ float smem[];
    const int tid = threadIdx.x;

    // cooperative weight staging
    for (int idx = tid; idx < 64 * 256; idx += 512)
        smem[W2S_OFF + (idx >> 8) * W2_STRIDE + (idx & 255)] = W2[idx];
    for (int idx = tid; idx < 16 * 64; idx += 512) {
        const int a = idx >> 6, c = idx & 63;
        const float w = W1[idx];
        smem[W1R_OFF + a * W1R_STRIDE + c] = w;
        smem[W1T_OFF + c * W1T_STRIDE + a] = w;
    }
    if (tid < 64) smem[B1S_OFF + tid] = b1[tid];
    if (tid < 256) smem[B2S_OFF + tid] = b2[tid];
    __syncthreads();

    const int warp = tid >> 5;
    const int lane = tid & 31;
    const int sub = lane & 7;
    const int g = lane >> 3;
    const int lp = warp * 4 + g;                   // block-local point 0..63
    int point = blockIdx.x * 64 + lp;
    if (point >= B) point = B - 1;                 // clamp (no divergence of syncs)

    const float* zp = z_in + point * 32;
    float xs0 = zp[sub];
    float xs1 = zp[sub + 8];
    float vs0 = zp[16 + sub];
    float vs1 = zp[24 + sub];

    const float t = *t_ptr;
    const int ns = *ns_ptr;
    const float dt = t / (float)ns;
    const float hdt = 0.5f * dt;
    const float dt6 = dt * (1.0f / 6.0f);

    for (int s = 0; s < ns; s++) {
        const float2 a1 = geo_dv(xs0, xs1, vs0, vs1, lane, sub, g, warp, lp);
        const float v20 = fmaf(hdt, a1.x, vs0);
        const float v21 = fmaf(hdt, a1.y, vs1);
        const float2 a2 = geo_dv(fmaf(hdt, vs0, xs0), fmaf(hdt, vs1, xs1),
                                 v20, v21, lane, sub, g, warp, lp);
        const float v30 = fmaf(hdt, a2.x, vs0);
        const float v31 = fmaf(hdt, a2.y, vs1);
        const float2 a3 = geo_dv(fmaf(hdt, v20, xs0), fmaf(hdt, v21, xs1),
                                 v30, v31, lane, sub, g, warp, lp);
        const float v40 = fmaf(dt, a3.x, vs0);
        const float v41 = fmaf(dt, a3.y, vs1);
        const float2 a4 = geo_dv(fmaf(dt, v30, xs0), fmaf(dt, v31, xs1),
                                 v40, v41, lane, sub, g, warp, lp);
        xs0 = fmaf(dt6, vs0 + 2.0f * v20 + 2.0f * v30 + v40, xs0);
        xs1 = fmaf(dt6, vs1 + 2.0f * v21 + 2.0f * v31 + v41, xs1);
        vs0 = fmaf(dt6, a1.x + 2.0f * a2.x + 2.0f * a3.x + a4.x, vs0);
        vs1 = fmaf(dt6, a1.y + 2.0f * a2.y + 2.0f * a3.y + a4.y, vs1);
    }

    float* op = z_out + point * 32;
    op[sub] = xs0;
    op[sub + 8] = xs1;
    op[16 + sub] = vs0;
    op[24 + sub] = vs1;
}

extern "C" void kernel_launch(void* const* d_in, const int* in_sizes, int n_in,
                              void* d_out, int out_size)
{
    const float* z  = (const float*)d_in[0];
    const float* t  = (const float*)d_in[1];
    const float* W1 = (const float*)d_in[2];
    const float* b1 = (const float*)d_in[3];
    const float* W2 = (const float*)d_in[4];
    const float* b2 = (const float*)d_in[5];
    const int*   ns = (const int*)d_in[6];
    float* out = (float*)d_out;

    const int B = in_sizes[0] / 32;
    const int grid = (B + 63) / 64;

    cudaFuncSetAttribute(NeuralGeodesicFlows_45784351375900_kernel,
                         cudaFuncAttributeMaxDynamicSharedMemorySize, SMEM_BYTES);
    NeuralGeodesicFlows_45784351375900_kernel<<<grid, 512, SMEM_BYTES>>>(
        z, t, W1, b1, W2, b2, ns, out, B);
}

// round 6
// speedup vs baseline: 1.4417x; 1.4417x over previous
#include <cuda_runtime.h>

#define FULLMASK 0xffffffffu

// ---- shared layout (float offsets), one 512-thread block, 64 points ----
#define W2_STRIDE 260
#define W1T_STRIDE 20
#define W1R_STRIDE 68
#define HW_STRIDE 68
#define UD_STRIDE 24
#define TS 20
#define TILE 328              // 328 % 32 == 8 (staggers the 4 per-warp tiles)

#define W2S_OFF 0             // 64*260 = 16640
#define W1T_OFF 16640         // 64*20  = 1280
#define W1R_OFF 17920         // 16*68  = 1088
#define B1S_OFF 19008         // 64
#define B2S_OFF 19072         // 256
#define HW_OFF  19328         // 64*68  = 4352   (w scratch, [pt][c])
#define HTS_OFF 23680         // 16 warps * 64*4 = 4096  (h transposed [c][4pt])
#define STT_OFF 27776         // 16 warps * 16*4 = 1024  (s transposed [q][4pt])
#define VTT_OFF 28800         // 16 warps * 16*4 = 1024  (v transposed [p][4pt])
#define USC_OFF 29824         // 64*24 = 1536
#define DSC_OFF 31360         // 1536
#define TILES_OFF 32896       // 64*328 = 20992
#define SMEM_FLOATS 53888
#define SMEM_BYTES (SMEM_FLOATS * 4)   // 215552

// One acceleration evaluation. Warp handles 4 points; lane=(g,sub),
// g=lane>>3 (point), sub=lane&7. All scratch is warp-private.
__device__ __noinline__ float2 geo_dv(float xe0, float xe1, float ve0, float ve1,
                                      int lane, int sub, int g, int warp)
{
    extern __shared__ float smem[];
    const float* W2s = smem + W2S_OFF;
    const float* W1t = smem + W1T_OFF;
    const float* W1r = smem + W1R_OFF;
    const float* b1s = smem + B1S_OFF;
    const float* b2s = smem + B2S_OFF;
    float* hw    = smem + HW_OFF;
    float* hts   = smem + HTS_OFF + warp * 256;
    float* stT   = smem + STT_OFF + warp * 64;
    float* vtT   = smem + VTT_OFF + warp * 64;
    float* usc   = smem + USC_OFF;
    float* dsc   = smem + DSC_OFF;
    float* tiles = smem + TILES_OFF + warp * 4 * TILE;

    const int gbase = lane & 24;
    const int lp = warp * 4 + g;

    __syncwarp();   // previous eval fully consumed
    vtT[sub * 4 + g] = ve0;
    vtT[(sub + 8) * 4 + g] = ve1;

    // ---- replicate x, v of own point ----
    float x[16], v[16];
#pragma unroll
    for (int a = 0; a < 8; a++) {
        x[a]     = __shfl_sync(FULLMASK, xe0, gbase + a);
        x[a + 8] = __shfl_sync(FULLMASK, xe1, gbase + a);
        v[a]     = __shfl_sync(FULLMASK, ve0, gbase + a);
        v[a + 8] = __shfl_sync(FULLMASK, ve1, gbase + a);
    }

    // ---- hidden layer: lane owns channels c = sub + 8j of its point ----
#pragma unroll
    for (int j = 0; j < 8; j++) {
        const int c = sub + 8 * j;
        float pre = b1s[c];
        const float4* wr = (const float4*)(W1t + c * W1T_STRIDE);
#pragma unroll
        for (int t = 0; t < 4; t++) {
            const float4 w = wr[t];
            pre = fmaf(w.x, x[4 * t + 0], pre);
            pre = fmaf(w.y, x[4 * t + 1], pre);
            pre = fmaf(w.z, x[4 * t + 2], pre);
            pre = fmaf(w.w, x[4 * t + 3], pre);
        }
        hts[c * 4 + g] = tanhf(pre);
    }
    __syncwarp();   // hts, vtT visible warp-wide

    // ---- A pass: one W2 sweep serves all 4 points, h via broadcast LDS ----
    float4 Aa[4], Ab[4];
    {
        const float4 bza = ((const float4*)b2s)[lane];
        const float4 bzb = ((const float4*)b2s)[32 + lane];
#pragma unroll
        for (int p = 0; p < 4; p++) { Aa[p] = bza; Ab[p] = bzb; }
    }
#pragma unroll 8
    for (int r = 0; r < 64; r++) {
        const float4 hv = *(const float4*)(hts + r * 4);
        const float4 wa = *(const float4*)(W2s + r * W2_STRIDE + 4 * lane);
        const float4 wb = *(const float4*)(W2s + r * W2_STRIDE + 128 + 4 * lane);
        Aa[0].x = fmaf(hv.x, wa.x, Aa[0].x); Aa[0].y = fmaf(hv.x, wa.y, Aa[0].y);
        Aa[0].z = fmaf(hv.x, wa.z, Aa[0].z); Aa[0].w = fmaf(hv.x, wa.w, Aa[0].w);
        Ab[0].x = fmaf(hv.x, wb.x, Ab[0].x); Ab[0].y = fmaf(hv.x, wb.y, Ab[0].y);
        Ab[0].z = fmaf(hv.x, wb.z, Ab[0].z); Ab[0].w = fmaf(hv.x, wb.w, Ab[0].w);
        Aa[1].x = fmaf(hv.y, wa.x, Aa[1].x); Aa[1].y = fmaf(hv.y, wa.y, Aa[1].y);
        Aa[1].z = fmaf(hv.y, wa.z, Aa[1].z); Aa[1].w = fmaf(hv.y, wa.w, Aa[1].w);
        Ab[1].x = fmaf(hv.y, wb.x, Ab[1].x); Ab[1].y = fmaf(hv.y, wb.y, Ab[1].y);
        Ab[1].z = fmaf(hv.y, wb.z, Ab[1].z); Ab[1].w = fmaf(hv.y, wb.w, Ab[1].w);
        Aa[2].x = fmaf(hv.z, wa.x, Aa[2].x); Aa[2].y = fmaf(hv.z, wa.y, Aa[2].y);
        Aa[2].z = fmaf(hv.z, wa.z, Aa[2].z); Aa[2].w = fmaf(hv.z, wa.w, Aa[2].w);
        Ab[2].x = fmaf(hv.z, wb.x, Ab[2].x); Ab[2].y = fmaf(hv.z, wb.y, Ab[2].y);
        Ab[2].z = fmaf(hv.z, wb.z, Ab[2].z); Ab[2].w = fmaf(hv.z, wb.w, Ab[2].w);
        Aa[3].x = fmaf(hv.w, wa.x, Aa[3].x); Aa[3].y = fmaf(hv.w, wa.y, Aa[3].y);
        Aa[3].z = fmaf(hv.w, wa.z, Aa[3].z); Aa[3].w = fmaf(hv.w, wa.w, Aa[3].w);
        Ab[3].x = fmaf(hv.w, wb.x, Ab[3].x); Ab[3].y = fmaf(hv.w, wb.y, Ab[3].y);
        Ab[3].z = fmaf(hv.w, wb.z, Ab[3].z); Ab[3].w = fmaf(hv.w, wb.w, Ab[3].w);
    }

    // ---- stage A tiles ----
    __syncwarp();
    {
        const int prow = lane >> 2;
        const int qcol = (lane & 3) * 4;
#pragma unroll
        for (int p = 0; p < 4; p++) {
            *(float4*)(tiles + p * TILE + prow * TS + qcol) = Aa[p];
            *(float4*)(tiles + p * TILE + (8 + prow) * TS + qcol) = Ab[p];
        }
    }
    __syncwarp();

    // ---- s = A^T v (own point), staged transposed ----
    {
        const float* myt = tiles + g * TILE;
        float s0 = 0.0f, s1 = 0.0f;
#pragma unroll
        for (int p = 0; p < 16; p++) {
            s0 = fmaf(myt[p * TS + sub], v[p], s0);
            s1 = fmaf(myt[p * TS + sub + 8], v[p], s1);
        }
        stT[sub * 4 + g] = s0;
        stT[(sub + 8) * 4 + g] = s1;
    }
    __syncwarp();

    // ---- m pass: lane owns W2 rows r0=lane, r1=lane+32 for ALL 4 points ----
    {
        float m0[4] = {0, 0, 0, 0}, m1[4] = {0, 0, 0, 0};
        const float* R0 = W2s + lane * W2_STRIDE;
        const float* R1 = W2s + (lane + 32) * W2_STRIDE;
#pragma unroll
        for (int qh = 0; qh < 2; qh++) {
            float sq[8][4];
#pragma unroll
            for (int q8 = 0; q8 < 8; q8++) {
                const float4 sv4 = *(const float4*)(stT + (qh * 8 + q8) * 4);
                sq[q8][0] = sv4.x; sq[q8][1] = sv4.y;
                sq[q8][2] = sv4.z; sq[q8][3] = sv4.w;
            }
#pragma unroll
            for (int p = 0; p < 16; p++) {
                const float4 vp = *(const float4*)(vtT + p * 4);
                const float4 wa0 = *(const float4*)(R0 + 16 * p + 8 * qh);
                const float4 wb0 = *(const float4*)(R0 + 16 * p + 8 * qh + 4);
                const float4 wa1 = *(const float4*)(R1 + 16 * p + 8 * qh);
                const float4 wb1 = *(const float4*)(R1 + 16 * p + 8 * qh + 4);
                float d0[4], d1[4];
#pragma unroll
                for (int pt = 0; pt < 4; pt++) {
                    d0[pt] = wa0.x * sq[0][pt];
                    d0[pt] = fmaf(wa0.y, sq[1][pt], d0[pt]);
                    d0[pt] = fmaf(wa0.z, sq[2][pt], d0[pt]);
                    d0[pt] = fmaf(wa0.w, sq[3][pt], d0[pt]);
                    d0[pt] = fmaf(wb0.x, sq[4][pt], d0[pt]);
                    d0[pt] = fmaf(wb0.y, sq[5][pt], d0[pt]);
                    d0[pt] = fmaf(wb0.z, sq[6][pt], d0[pt]);
                    d0[pt] = fmaf(wb0.w, sq[7][pt], d0[pt]);
                    d1[pt] = wa1.x * sq[0][pt];
                    d1[pt] = fmaf(wa1.y, sq[1][pt], d1[pt]);
                    d1[pt] = fmaf(wa1.z, sq[2][pt], d1[pt]);
                    d1[pt] = fmaf(wa1.w, sq[3][pt], d1[pt]);
                    d1[pt] = fmaf(wb1.x, sq[4][pt], d1[pt]);
                    d1[pt] = fmaf(wb1.y, sq[5][pt], d1[pt]);
                    d1[pt] = fmaf(wb1.z, sq[6][pt], d1[pt]);
                    d1[pt] = fmaf(wb1.w, sq[7][pt], d1[pt]);
                }
                m0[0] = fmaf(vp.x, d0[0], m0[0]); m0[1] = fmaf(vp.y, d0[1], m0[1]);
                m0[2] = fmaf(vp.z, d0[2], m0[2]); m0[3] = fmaf(vp.w, d0[3], m0[3]);
                m1[0] = fmaf(vp.x, d1[0], m1[0]); m1[1] = fmaf(vp.y, d1[1], m1[1]);
                m1[2] = fmaf(vp.z, d1[2], m1[2]); m1[3] = fmaf(vp.w, d1[3], m1[3]);
            }
        }
        // epilogue: w[pt][c] = 2*(1-h^2)*m,  th from hts
#pragma unroll
        for (int pt = 0; pt < 4; pt++) {
            const float h0 = hts[lane * 4 + pt];
            const float h1 = hts[(lane + 32) * 4 + pt];
            const float th0 = fmaf(-h0, h0, 1.0f);
            const float th1 = fmaf(-h1, h1, 1.0f);
            hw[(warp * 4 + pt) * HW_STRIDE + lane] = 2.0f * th0 * m0[pt];
            hw[(warp * 4 + pt) * HW_STRIDE + lane + 32] = 2.0f * th1 * m1[pt];
        }
    }
    __syncwarp();

    // ---- u rows sub, sub+8 of own point ----
    {
        float u0 = 0.0f, u1 = 0.0f;
        const float4* wr0 = (const float4*)(W1r + sub * W1R_STRIDE);
        const float4* wr1 = (const float4*)(W1r + (sub + 8) * W1R_STRIDE);
        const float4* wc = (const float4*)(hw + lp * HW_STRIDE);
#pragma unroll
        for (int t = 0; t < 16; t++) {
            const float4 cc = wc[t];
            const float4 a0 = wr0[t];
            const float4 a1 = wr1[t];
            u0 = fmaf(a0.x, cc.x, u0); u0 = fmaf(a0.y, cc.y, u0);
            u0 = fmaf(a0.z, cc.z, u0); u0 = fmaf(a0.w, cc.w, u0);
            u1 = fmaf(a1.x, cc.x, u1); u1 = fmaf(a1.y, cc.y, u1);
            u1 = fmaf(a1.z, cc.z, u1); u1 = fmaf(a1.w, cc.w, u1);
        }
        usc[lp * UD_STRIDE + sub] = u0;
        usc[lp * UD_STRIDE + sub + 8] = u1;
    }
    __syncwarp();

    // ---- g-build + SPD solve: interleaved dual chains (points half & 2+half) ----
    const int half = lane >> 4;
    const int i16 = lane & 15;
    {
        const float* TA = tiles + half * TILE;
        const float* TB = tiles + (2 + half) * TILE;

        float growA[16], growB[16];
        {
            float ar[16];
#pragma unroll
            for (int t = 0; t < 4; t++) {
                const float4 w = *(const float4*)(TA + i16 * TS + 4 * t);
                ar[4 * t + 0] = w.x; ar[4 * t + 1] = w.y;
                ar[4 * t + 2] = w.z; ar[4 * t + 3] = w.w;
            }
#pragma unroll
            for (int jr = 0; jr < 16; jr++) {
                float gj = (jr == i16) ? 1.0f : 0.0f;
#pragma unroll
                for (int t = 0; t < 4; t++) {
                    const float4 w = *(const float4*)(TA + jr * TS + 4 * t);
                    gj = fmaf(ar[4 * t + 0], w.x, gj);
                    gj = fmaf(ar[4 * t + 1], w.y, gj);
                    gj = fmaf(ar[4 * t + 2], w.z, gj);
                    gj = fmaf(ar[4 * t + 3], w.w, gj);
                }
                growA[jr] = gj;
            }
#pragma unroll
            for (int t = 0; t < 4; t++) {
                const float4 w = *(const float4*)(TB + i16 * TS + 4 * t);
                ar[4 * t + 0] = w.x; ar[4 * t + 1] = w.y;
                ar[4 * t + 2] = w.z; ar[4 * t + 3] = w.w;
            }
#pragma unroll
            for (int jr = 0; jr < 16; jr++) {
                float gj = (jr == i16) ? 1.0f : 0.0f;
#pragma unroll
                for (int t = 0; t < 4; t++) {
                    const float4 w = *(const float4*)(TB + jr * TS + 4 * t);
                    gj = fmaf(ar[4 * t + 0], w.x, gj);
                    gj = fmaf(ar[4 * t + 1], w.y, gj);
                    gj = fmaf(ar[4 * t + 2], w.z, gj);
                    gj = fmaf(ar[4 * t + 3], w.w, gj);
                }
                growB[jr] = gj;
            }
        }
        float rhsA = usc[(warp * 4 + half) * UD_STRIDE + i16];
        float rhsB = usc[(warp * 4 + 2 + half) * UD_STRIDE + i16];

#pragma unroll
        for (int k = 0; k < 15; k++) {
            const float pivA = __shfl_sync(FULLMASK, growA[k], k, 16);
            const float pivB = __shfl_sync(FULLMASK, growB[k], k, 16);
            const float prA = __shfl_sync(FULLMASK, rhsA, k, 16);
            const float prB = __shfl_sync(FULLMASK, rhsB, k, 16);
            const float facA = growA[k] * __fdividef(1.0f, pivA);
            const float facB = growB[k] * __fdividef(1.0f, pivB);
            const bool act = (i16 > k);
#pragma unroll
            for (int q = k + 1; q < 16; q++) {
                const float pqA = __shfl_sync(FULLMASK, growA[q], k, 16);
                const float pqB = __shfl_sync(FULLMASK, growB[q], k, 16);
                if (act) {
                    growA[q] = fmaf(-facA, pqA, growA[q]);
                    growB[q] = fmaf(-facB, pqB, growB[q]);
                }
            }
            if (act) {
                rhsA = fmaf(-facA, prA, rhsA);
                rhsB = fmaf(-facB, prB, rhsB);
            }
        }
        float dvlA = 0.0f, dvlB = 0.0f;
#pragma unroll
        for (int k = 15; k >= 0; k--) {
            const float numA = __shfl_sync(FULLMASK, rhsA, k, 16);
            const float numB = __shfl_sync(FULLMASK, rhsB, k, 16);
            const float denA = __shfl_sync(FULLMASK, growA[k], k, 16);
            const float denB = __shfl_sync(FULLMASK, growB[k], k, 16);
            const float ykA = __fdividef(numA, denA);
            const float ykB = __fdividef(numB, denB);
            if (i16 < k) {
                rhsA = fmaf(-growA[k], ykA, rhsA);
                rhsB = fmaf(-growB[k], ykB, rhsB);
            }
            if (i16 == k) { dvlA = -0.5f * ykA; dvlB = -0.5f * ykB; }
        }
        dsc[(warp * 4 + half) * UD_STRIDE + i16] = dvlA;
        dsc[(warp * 4 + 2 + half) * UD_STRIDE + i16] = dvlB;
    }
    __syncwarp();

    float2 res;
    res.x = dsc[lp * UD_STRIDE + sub];
    res.y = dsc[lp * UD_STRIDE + sub + 8];
    return res;
}

__global__ __launch_bounds__(512, 1)
void NeuralGeodesicFlows_45784351375900_kernel(
    const float* __restrict__ z_in,
    const float* __restrict__ t_ptr,
    const float* __restrict__ W1,
    const float* __restrict__ b1,
    const float* __restrict__ W2,
    const float* __restrict__ b2,
    const int* __restrict__ ns_ptr,
    float* __restrict__ z_out,
    int B)
{
    extern __shared__ float smem[];
    const int tid = threadIdx.x;

    for (int idx = tid; idx < 64 * 256; idx += 512)
        smem[W2S_OFF + (idx >> 8) * W2_STRIDE + (idx & 255)] = W2[idx];
    for (int idx = tid; idx < 16 * 64; idx += 512) {
        const int a = idx >> 6, c = idx & 63;
        const float w = W1[idx];
        smem[W1R_OFF + a * W1R_STRIDE + c] = w;
        smem[W1T_OFF + c * W1T_STRIDE + a] = w;
    }
    if (tid < 64) smem[B1S_OFF + tid] = b1[tid];
    if (tid < 256) smem[B2S_OFF + tid] = b2[tid];
    __syncthreads();

    const int warp = tid >> 5;
    const int lane = tid & 31;
    const int sub = lane & 7;
    const int g = lane >> 3;
    const int point = blockIdx.x * 64 + warp * 4 + g;
    if (point >= B) return;

    const float* zp = z_in + point * 32;
    float xs0 = zp[sub];
    float xs1 = zp[sub + 8];
    float vs0 = zp[16 + sub];
    float vs1 = zp[24 + sub];

    const float t = *t_ptr;
    const int ns = *ns_ptr;
    const float dt = t / (float)ns;
    const float hdt = 0.5f * dt;
    const float dt6 = dt * (1.0f / 6.0f);

    for (int s = 0; s < ns; s++) {
        const float2 a1 = geo_dv(xs0, xs1, vs0, vs1, lane, sub, g, warp);
        const float v20 = fmaf(hdt, a1.x, vs0);
        const float v21 = fmaf(hdt, a1.y, vs1);
        const float2 a2 = geo_dv(fmaf(hdt, vs0, xs0), fmaf(hdt, vs1, xs1),
                                 v20, v21, lane, sub, g, warp);
        const float v30 = fmaf(hdt, a2.x, vs0);
        const float v31 = fmaf(hdt, a2.y, vs1);
        const float2 a3 = geo_dv(fmaf(hdt, v20, xs0), fmaf(hdt, v21, xs1),
                                 v30, v31, lane, sub, g, warp);
        const float v40 = fmaf(dt, a3.x, vs0);
        const float v41 = fmaf(dt, a3.y, vs1);
        const float2 a4 = geo_dv(fmaf(dt, v30, xs0), fmaf(dt, v31, xs1),
                                 v40, v41, lane, sub, g, warp);
        xs0 = fmaf(dt6, vs0 + 2.0f * v20 + 2.0f * v30 + v40, xs0);
        xs1 = fmaf(dt6, vs1 + 2.0f * v21 + 2.0f * v31 + v41, xs1);
        vs0 = fmaf(dt6, a1.x + 2.0f * a2.x + 2.0f * a3.x + a4.x, vs0);
        vs1 = fmaf(dt6, a1.y + 2.0f * a2.y + 2.0f * a3.y + a4.y, vs1);
    }

    float* op = z_out + point * 32;
    op[sub] = xs0;
    op[sub + 8] = xs1;
    op[16 + sub] = vs0;
    op[24 + sub] = vs1;
}

extern "C" void kernel_launch(void* const* d_in, const int* in_sizes, int n_in,
                              void* d_out, int out_size)
{
    const float* z  = (const float*)d_in[0];
    const float* t  = (const float*)d_in[1];
    const float* W1 = (const float*)d_in[2];
    const float* b1 = (const float*)d_in[3];
    const float* W2 = (const float*)d_in[4];
    const float* b2 = (const float*)d_in[5];
    const int*   ns = (const int*)d_in[6];
    float* out = (float*)d_out;

    const int B = in_sizes[0] / 32;
    const int grid = (B + 63) / 64;

    cudaFuncSetAttribute(NeuralGeodesicFlows_45784351375900_kernel,
                         cudaFuncAttributeMaxDynamicSharedMemorySize, SMEM_BYTES);
    NeuralGeodesicFlows_45784351375900_kernel<<<grid, 512, SMEM_BYTES>>>(
        z, t, W1, b1, W2, b2, ns, out, B);
}

// round 8
// speedup vs baseline: 1.5228x; 1.0562x over previous
#include <cuda_runtime.h>

#define FULLMASK 0xffffffffu
typedef unsigned long long u64;

__device__ __forceinline__ u64 ffma2(u64 a, u64 b, u64 c) {
    u64 r;
    asm("fma.rn.f32x2 %0, %1, %2, %3;" : "=l"(r) : "l"(a), "l"(b), "l"(c));
    return r;
}
__device__ __forceinline__ u64 dup2f(float v) {
    u64 r;
    asm("mov.b64 %0, {%1, %1};" : "=l"(r) : "f"(v));
    return r;
}
__device__ __forceinline__ float2 unpk(u64 p) {
    float2 f;
    asm("mov.b64 {%0, %1}, %2;" : "=f"(f.x), "=f"(f.y) : "l"(p));
    return f;
}

// ---- shared layout (float offsets), one 512-thread block, 64 points ----
#define W2_STRIDE 260
#define W1T_STRIDE 20
#define W1R_STRIDE 68
#define HW_STRIDE 68
#define UD_STRIDE 24
#define TS 20
#define TILE 324              // 324*4=1296 bytes (16B aligned), %32==4 stagger

#define W2S_OFF 0             // 16640
#define W1T_OFF 16640         // 1280
#define W1R_OFF 17920         // 1088
#define B1S_OFF 19008         // 64
#define B2S_OFF 19072         // 256
#define HW_OFF  19328         // 64*68 = 4352
#define HTS2_OFF 23680        // 16 warps * 512 floats (= 256 u64 {h,h} per warp)
#define STT_OFF 31872         // 16 warps * 64
#define VTT_OFF 32896         // 16 warps * 64
#define USC_OFF 33920         // 64*24
#define DSC_OFF 35456         // 64*24
#define TILES_OFF 36992       // 64*324 = 20736
#define SMEM_FLOATS 57728
#define SMEM_BYTES (SMEM_FLOATS * 4)   // 230912

// One acceleration evaluation. Warp handles 4 points; lane=(g,sub),
// g=lane>>3 (point), sub=lane&7. All scratch is warp-private.
__device__ __noinline__ float2 geo_dv(float xe0, float xe1, float ve0, float ve1,
                                      int lane, int sub, int g, int warp)
{
    extern __shared__ float smem[];
    const float* W2s = smem + W2S_OFF;
    const float* W1t = smem + W1T_OFF;
    const float* W1r = smem + W1R_OFF;
    const float* b1s = smem + B1S_OFF;
    const float* b2s = smem + B2S_OFF;
    float* hw    = smem + HW_OFF;
    u64*   hts2  = (u64*)(smem + HTS2_OFF) + warp * 256;   // [c*4 + pt] = {h,h}
    float* stT   = smem + STT_OFF + warp * 64;
    float* vtT   = smem + VTT_OFF + warp * 64;
    float* usc   = smem + USC_OFF;
    float* dsc   = smem + DSC_OFF;
    float* tiles = smem + TILES_OFF + warp * 4 * TILE;

    const int gbase = lane & 24;
    const int lp = warp * 4 + g;

    __syncwarp();   // previous eval fully consumed
    vtT[sub * 4 + g] = ve0;
    vtT[(sub + 8) * 4 + g] = ve1;

    // ---- replicate x, v of own point ----
    float x[16], v[16];
#pragma unroll
    for (int a = 0; a < 8; a++) {
        x[a]     = __shfl_sync(FULLMASK, xe0, gbase + a);
        x[a + 8] = __shfl_sync(FULLMASK, xe1, gbase + a);
        v[a]     = __shfl_sync(FULLMASK, ve0, gbase + a);
        v[a + 8] = __shfl_sync(FULLMASK, ve1, gbase + a);
    }

    // ---- hidden layer: lane owns channels c = sub + 8j of its point ----
#pragma unroll
    for (int j = 0; j < 8; j++) {
        const int c = sub + 8 * j;
        float pre = b1s[c];
        const float4* wr = (const float4*)(W1t + c * W1T_STRIDE);
#pragma unroll
        for (int t = 0; t < 4; t++) {
            const float4 w = wr[t];
            pre = fmaf(w.x, x[4 * t + 0], pre);
            pre = fmaf(w.y, x[4 * t + 1], pre);
            pre = fmaf(w.z, x[4 * t + 2], pre);
            pre = fmaf(w.w, x[4 * t + 3], pre);
        }
        hts2[c * 4 + g] = dup2f(tanhf(pre));
    }
    __syncwarp();   // hts2, vtT visible warp-wide

    // ---- A pass: one W2 sweep serves all 4 points, packed col-pairs ----
    // lane owns flat cols [4l,4l+4) (a) and [128+4l,..) (b); each as 2 f32x2.
    u64 a0[4], a1[4], bb0[4], bb1[4];
    {
        const ulonglong2 bza = *(const ulonglong2*)(b2s + 4 * lane);
        const ulonglong2 bzb = *(const ulonglong2*)(b2s + 128 + 4 * lane);
#pragma unroll
        for (int pt = 0; pt < 4; pt++) {
            a0[pt] = bza.x; a1[pt] = bza.y;
            bb0[pt] = bzb.x; bb1[pt] = bzb.y;
        }
    }
#pragma unroll 8
    for (int r = 0; r < 64; r++) {
        const ulonglong2 h01 = *(const ulonglong2*)(hts2 + r * 4);
        const ulonglong2 h23 = *(const ulonglong2*)(hts2 + r * 4 + 2);
        const ulonglong2 wa = *(const ulonglong2*)(W2s + r * W2_STRIDE + 4 * lane);
        const ulonglong2 wb = *(const ulonglong2*)(W2s + r * W2_STRIDE + 128 + 4 * lane);
        a0[0] = ffma2(h01.x, wa.x, a0[0]);  a1[0] = ffma2(h01.x, wa.y, a1[0]);
        bb0[0] = ffma2(h01.x, wb.x, bb0[0]); bb1[0] = ffma2(h01.x, wb.y, bb1[0]);
        a0[1] = ffma2(h01.y, wa.x, a0[1]);  a1[1] = ffma2(h01.y, wa.y, a1[1]);
        bb0[1] = ffma2(h01.y, wb.x, bb0[1]); bb1[1] = ffma2(h01.y, wb.y, bb1[1]);
        a0[2] = ffma2(h23.x, wa.x, a0[2]);  a1[2] = ffma2(h23.x, wa.y, a1[2]);
        bb0[2] = ffma2(h23.x, wb.x, bb0[2]); bb1[2] = ffma2(h23.x, wb.y, bb1[2]);
        a0[3] = ffma2(h23.y, wa.x, a0[3]);  a1[3] = ffma2(h23.y, wa.y, a1[3]);
        bb0[3] = ffma2(h23.y, wb.x, bb0[3]); bb1[3] = ffma2(h23.y, wb.y, bb1[3]);
    }

    // ---- stage A tiles (stores are bit-identical to float4 stores) ----
    __syncwarp();
    {
        const int prow = lane >> 2;
        const int qcol = (lane & 3) * 4;
#pragma unroll
        for (int pt = 0; pt < 4; pt++) {
            *(ulonglong2*)(tiles + pt * TILE + prow * TS + qcol) =
                make_ulonglong2(a0[pt], a1[pt]);
            *(ulonglong2*)(tiles + pt * TILE + (8 + prow) * TS + qcol) =
                make_ulonglong2(bb0[pt], bb1[pt]);
        }
    }
    __syncwarp();

    // ---- s = A^T v (own point), staged transposed ----
    {
        const float* myt = tiles + g * TILE;
        float s0 = 0.0f, s1 = 0.0f;
#pragma unroll
        for (int p = 0; p < 16; p++) {
            s0 = fmaf(myt[p * TS + sub], v[p], s0);
            s1 = fmaf(myt[p * TS + sub + 8], v[p], s1);
        }
        stT[sub * 4 + g] = s0;
        stT[(sub + 8) * 4 + g] = s1;
    }
    __syncwarp();

    // ---- m pass: lane owns W2 rows r0=lane, r1=lane+32 for ALL 4 points ----
    // pt-pair packed accumulators; s, v free-packed from stT/vtT.
    {
        u64 m0a = 0, m0b = 0, m1a = 0, m1b = 0;
        const float* R0 = W2s + lane * W2_STRIDE;
        const float* R1 = W2s + (lane + 32) * W2_STRIDE;
#pragma unroll
        for (int qh = 0; qh < 2; qh++) {
            u64 sqa[8], sqb[8];
#pragma unroll
            for (int q8 = 0; q8 < 8; q8++) {
                const ulonglong2 sv = *(const ulonglong2*)(stT + (qh * 8 + q8) * 4);
                sqa[q8] = sv.x; sqb[q8] = sv.y;
            }
#pragma unroll
            for (int p = 0; p < 16; p++) {
                const ulonglong2 vp2 = *(const ulonglong2*)(vtT + p * 4);
                const float4 wa0 = *(const float4*)(R0 + 16 * p + 8 * qh);
                const float4 wb0 = *(const float4*)(R0 + 16 * p + 8 * qh + 4);
                const float4 wa1 = *(const float4*)(R1 + 16 * p + 8 * qh);
                const float4 wb1 = *(const float4*)(R1 + 16 * p + 8 * qh + 4);
                u64 d0a = 0, d0b = 0, d1a = 0, d1b = 0;
                u64 wd;
                wd = dup2f(wa0.x); d0a = ffma2(wd, sqa[0], d0a); d0b = ffma2(wd, sqb[0], d0b);
                wd = dup2f(wa0.y); d0a = ffma2(wd, sqa[1], d0a); d0b = ffma2(wd, sqb[1], d0b);
                wd = dup2f(wa0.z); d0a = ffma2(wd, sqa[2], d0a); d0b = ffma2(wd, sqb[2], d0b);
                wd = dup2f(wa0.w); d0a = ffma2(wd, sqa[3], d0a); d0b = ffma2(wd, sqb[3], d0b);
                wd = dup2f(wb0.x); d0a = ffma2(wd, sqa[4], d0a); d0b = ffma2(wd, sqb[4], d0b);
                wd = dup2f(wb0.y); d0a = ffma2(wd, sqa[5], d0a); d0b = ffma2(wd, sqb[5], d0b);
                wd = dup2f(wb0.z); d0a = ffma2(wd, sqa[6], d0a); d0b = ffma2(wd, sqb[6], d0b);
                wd = dup2f(wb0.w); d0a = ffma2(wd, sqa[7], d0a); d0b = ffma2(wd, sqb[7], d0b);
                wd = dup2f(wa1.x); d1a = ffma2(wd, sqa[0], d1a); d1b = ffma2(wd, sqb[0], d1b);
                wd = dup2f(wa1.y); d1a = ffma2(wd, sqa[1], d1a); d1b = ffma2(wd, sqb[1], d1b);
                wd = dup2f(wa1.z); d1a = ffma2(wd, sqa[2], d1a); d1b = ffma2(wd, sqb[2], d1b);
                wd = dup2f(wa1.w); d1a = ffma2(wd, sqa[3], d1a); d1b = ffma2(wd, sqb[3], d1b);
                wd = dup2f(wb1.x); d1a = ffma2(wd, sqa[4], d1a); d1b = ffma2(wd, sqb[4], d1b);
                wd = dup2f(wb1.y); d1a = ffma2(wd, sqa[5], d1a); d1b = ffma2(wd, sqb[5], d1b);
                wd = dup2f(wb1.z); d1a = ffma2(wd, sqa[6], d1a); d1b = ffma2(wd, sqb[6], d1b);
                wd = dup2f(wb1.w); d1a = ffma2(wd, sqa[7], d1a); d1b = ffma2(wd, sqb[7], d1b);
                m0a = ffma2(vp2.x, d0a, m0a); m0b = ffma2(vp2.y, d0b, m0b);
                m1a = ffma2(vp2.x, d1a, m1a); m1b = ffma2(vp2.y, d1b, m1b);
            }
        }
        const float2 m001 = unpk(m0a), m023 = unpk(m0b);
        const float2 m101 = unpk(m1a), m123 = unpk(m1b);
        const float m0[4] = {m001.x, m001.y, m023.x, m023.y};
        const float m1[4] = {m101.x, m101.y, m123.x, m123.y};
#pragma unroll
        for (int pt = 0; pt < 4; pt++) {
            const float h0 = unpk(hts2[lane * 4 + pt]).x;
            const float h1 = unpk(hts2[(lane + 32) * 4 + pt]).x;
            const float th0 = fmaf(-h0, h0, 1.0f);
            const float th1 = fmaf(-h1, h1, 1.0f);
            hw[(warp * 4 + pt) * HW_STRIDE + lane] = 2.0f * th0 * m0[pt];
            hw[(warp * 4 + pt) * HW_STRIDE + lane + 32] = 2.0f * th1 * m1[pt];
        }
    }
    __syncwarp();

    // ---- u rows sub, sub+8 of own point (packed) ----
    {
        u64 u0p = 0, u1p = 0;
        const float* wc = hw + lp * HW_STRIDE;
        const float* r0 = W1r + sub * W1R_STRIDE;
        const float* r1 = W1r + (sub + 8) * W1R_STRIDE;
#pragma unroll
        for (int t = 0; t < 16; t++) {
            const ulonglong2 cc = *(const ulonglong2*)(wc + 4 * t);
            const ulonglong2 w0 = *(const ulonglong2*)(r0 + 4 * t);
            const ulonglong2 w1 = *(const ulonglong2*)(r1 + 4 * t);
            u0p = ffma2(w0.x, cc.x, u0p); u0p = ffma2(w0.y, cc.y, u0p);
            u1p = ffma2(w1.x, cc.x, u1p); u1p = ffma2(w1.y, cc.y, u1p);
        }
        const float2 f0 = unpk(u0p);
        const float2 f1 = unpk(u1p);
        usc[lp * UD_STRIDE + sub] = f0.x + f0.y;
        usc[lp * UD_STRIDE + sub + 8] = f1.x + f1.y;
    }
    __syncwarp();

    // ---- g-build (packed) + interleaved dual SPD solve ----
    const int half = lane >> 4;
    const int i16 = lane & 15;
    {
        const float* TA = tiles + half * TILE;
        const float* TB = tiles + (2 + half) * TILE;

        float growA[16], growB[16];
        {
            u64 ar2[8];
#pragma unroll
            for (int t = 0; t < 4; t++) {
                const ulonglong2 w = *(const ulonglong2*)(TA + i16 * TS + 4 * t);
                ar2[2 * t] = w.x; ar2[2 * t + 1] = w.y;
            }
#pragma unroll
            for (int jr = 0; jr < 16; jr++) {
                u64 gp = 0;
#pragma unroll
                for (int t = 0; t < 4; t++) {
                    const ulonglong2 w = *(const ulonglong2*)(TA + jr * TS + 4 * t);
                    gp = ffma2(ar2[2 * t], w.x, gp);
                    gp = ffma2(ar2[2 * t + 1], w.y, gp);
                }
                const float2 gf = unpk(gp);
                growA[jr] = gf.x + gf.y + ((jr == i16) ? 1.0f : 0.0f);
            }
#pragma unroll
            for (int t = 0; t < 4; t++) {
                const ulonglong2 w = *(const ulonglong2*)(TB + i16 * TS + 4 * t);
                ar2[2 * t] = w.x; ar2[2 * t + 1] = w.y;
            }
#pragma unroll
            for (int jr = 0; jr < 16; jr++) {
                u64 gp = 0;
#pragma unroll
                for (int t = 0; t < 4; t++) {
                    const ulonglong2 w = *(const ulonglong2*)(TB + jr * TS + 4 * t);
                    gp = ffma2(ar2[2 * t], w.x, gp);
                    gp = ffma2(ar2[2 * t + 1], w.y, gp);
                }
                const float2 gf = unpk(gp);
                growB[jr] = gf.x + gf.y + ((jr == i16) ? 1.0f : 0.0f);
            }
        }
        float rhsA = usc[(warp * 4 + half) * UD_STRIDE + i16];
        float rhsB = usc[(warp * 4 + 2 + half) * UD_STRIDE + i16];

#pragma unroll
        for (int k = 0; k < 15; k++) {
            const float pivA = __shfl_sync(FULLMASK, growA[k], k, 16);
            const float pivB = __shfl_sync(FULLMASK, growB[k], k, 16);
            const float prA = __shfl_sync(FULLMASK, rhsA, k, 16);
            const float prB = __shfl_sync(FULLMASK, rhsB, k, 16);
            const float facA = growA[k] * __fdividef(1.0f, pivA);
            const float facB = growB[k] * __fdividef(1.0f, pivB);
            const bool act = (i16 > k);
#pragma unroll
            for (int q = k + 1; q < 16; q++) {
                const float pqA = __shfl_sync(FULLMASK, growA[q], k, 16);
                const float pqB = __shfl_sync(FULLMASK, growB[q], k, 16);
                if (act) {
                    growA[q] = fmaf(-facA, pqA, growA[q]);
                    growB[q] = fmaf(-facB, pqB, growB[q]);
                }
            }
            if (act) {
                rhsA = fmaf(-facA, prA, rhsA);
                rhsB = fmaf(-facB, prB, rhsB);
            }
        }
        float dvlA = 0.0f, dvlB = 0.0f;
#pragma unroll
        for (int k = 15; k >= 0; k--) {
            const float numA = __shfl_sync(FULLMASK, rhsA, k, 16);
            const float numB = __shfl_sync(FULLMASK, rhsB, k, 16);
            const float denA = __shfl_sync(FULLMASK, growA[k], k, 16);
            const float denB = __shfl_sync(FULLMASK, growB[k], k, 16);
            const float ykA = __fdividef(numA, denA);
            const float ykB = __fdividef(numB, denB);
            if (i16 < k) {
                rhsA = fmaf(-growA[k], ykA, rhsA);
                rhsB = fmaf(-growB[k], ykB, rhsB);
            }
            if (i16 == k) { dvlA = -0.5f * ykA; dvlB = -0.5f * ykB; }
        }
        dsc[(warp * 4 + half) * UD_STRIDE + i16] = dvlA;
        dsc[(warp * 4 + 2 + half) * UD_STRIDE + i16] = dvlB;
    }
    __syncwarp();

    float2 res;
    res.x = dsc[lp * UD_STRIDE + sub];
    res.y = dsc[lp * UD_STRIDE + sub + 8];
    return res;
}

__global__ __launch_bounds__(512, 1)
void NeuralGeodesicFlows_45784351375900_kernel(
    const float* __restrict__ z_in,
    const float* __restrict__ t_ptr,
    const float* __restrict__ W1,
    const float* __restrict__ b1,
    const float* __restrict__ W2,
    const float* __restrict__ b2,
    const int* __restrict__ ns_ptr,
    float* __restrict__ z_out,
    int B)
{
    extern __shared__ float smem[];
    const int tid = threadIdx.x;

    for (int idx = tid; idx < 64 * 256; idx += 512)
        smem[W2S_OFF + (idx >> 8) * W2_STRIDE + (idx & 255)] = W2[idx];
    for (int idx = tid; idx < 16 * 64; idx += 512) {
        const int a = idx >> 6, c = idx & 63;
        const float w = W1[idx];
        smem[W1R_OFF + a * W1R_STRIDE + c] = w;
        smem[W1T_OFF + c * W1T_STRIDE + a] = w;
    }
    if (tid < 64) smem[B1S_OFF + tid] = b1[tid];
    if (tid < 256) smem[B2S_OFF + tid] = b2[tid];
    __syncthreads();

    const int warp = tid >> 5;
    const int lane = tid & 31;
    const int sub = lane & 7;
    const int g = lane >> 3;
    const int point = blockIdx.x * 64 + warp * 4 + g;
    if (point >= B) return;

    const float* zp = z_in + point * 32;
    float xs0 = zp[sub];
    float xs1 = zp[sub + 8];
    float vs0 = zp[16 + sub];
    float vs1 = zp[24 + sub];

    const float t = *t_ptr;
    const int ns = *ns_ptr;
    const float dt = t / (float)ns;
    const float hdt = 0.5f * dt;
    const float dt6 = dt * (1.0f / 6.0f);

    for (int s = 0; s < ns; s++) {
        const float2 a1 = geo_dv(xs0, xs1, vs0, vs1, lane, sub, g, warp);
        const float v20 = fmaf(hdt, a1.x, vs0);
        const float v21 = fmaf(hdt, a1.y, vs1);
        const float2 a2 = geo_dv(fmaf(hdt, vs0, xs0), fmaf(hdt, vs1, xs1),
                                 v20, v21, lane, sub, g, warp);
        const float v30 = fmaf(hdt, a2.x, vs0);
        const float v31 = fmaf(hdt, a2.y, vs1);
        const float2 a3 = geo_dv(fmaf(hdt, v20, xs0), fmaf(hdt, v21, xs1),
                                 v30, v31, lane, sub, g, warp);
        const float v40 = fmaf(dt, a3.x, vs0);
        const float v41 = fmaf(dt, a3.y, vs1);
        const float2 a4 = geo_dv(fmaf(dt, v30, xs0), fmaf(dt, v31, xs1),
                                 v40, v41, lane, sub, g, warp);
        xs0 = fmaf(dt6, vs0 + 2.0f * v20 + 2.0f * v30 + v40, xs0);
        xs1 = fmaf(dt6, vs1 + 2.0f * v21 + 2.0f * v31 + v41, xs1);
        vs0 = fmaf(dt6, a1.x + 2.0f * a2.x + 2.0f * a3.x + a4.x, vs0);
        vs1 = fmaf(dt6, a1.y + 2.0f * a2.y + 2.0f * a3.y + a4.y, vs1);
    }

    float* op = z_out + point * 32;
    op[sub] = xs0;
    op[sub + 8] = xs1;
    op[16 + sub] = vs0;
    op[24 + sub] = vs1;
}

extern "C" void kernel_launch(void* const* d_in, const int* in_sizes, int n_in,
                              void* d_out, int out_size)
{
    const float* z  = (const float*)d_in[0];
    const float* t  = (const float*)d_in[1];
    const float* W1 = (const float*)d_in[2];
    const float* b1 = (const float*)d_in[3];
    const float* W2 = (const float*)d_in[4];
    const float* b2 = (const float*)d_in[5];
    const int*   ns = (const int*)d_in[6];
    float* out = (float*)d_out;

    const int B = in_sizes[0] / 32;
    const int grid = (B + 63) / 64;

    cudaFuncSetAttribute(NeuralGeodesicFlows_45784351375900_kernel,
                         cudaFuncAttributeMaxDynamicSharedMemorySize, SMEM_BYTES);
    NeuralGeodesicFlows_45784351375900_kernel<<<grid, 512, SMEM_BYTES>>>(
        z, t, W1, b1, W2, b2, ns, out, B);
}